// round 2
// baseline (speedup 1.0000x reference)
#include <cuda_runtime.h>
#include <cuda_bf16.h>

#define NN 100000
#define NE 640000
#define NL 100000
#define INC 128
#define HIDC 128
#define OUTC 64

// Scratch (device globals: allocation-free rule)
__device__ float g_agg[(size_t)NN * 128];   // reused by both layers (both 128 wide)
__device__ float g_cnt[NN];
__device__ float g_inv[NN];
__device__ float g_h[(size_t)NN * HIDC];
__device__ float g_z[(size_t)NN * OUTC];

// ---------------------------------------------------------------------------
// Zero agg (+ optionally cnt)
// ---------------------------------------------------------------------------
__global__ void zero_kernel(float4* agg4, int n4, float* cnt, int nc) {
    int i = blockIdx.x * blockDim.x + threadIdx.x;
    int stride = gridDim.x * blockDim.x;
    for (int j = i; j < n4; j += stride)
        agg4[j] = make_float4(0.f, 0.f, 0.f, 0.f);
    if (cnt) {
        for (int j = i; j < nc; j += stride) cnt[j] = 0.f;
    }
}

// ---------------------------------------------------------------------------
// Scatter-mean numerator: warp per edge, lane per float4 (128 floats/row).
// Indices are int32 (harness converts int64 -> int32).
// ---------------------------------------------------------------------------
__global__ void scatter_kernel(const float* __restrict__ feat,
                               const int* __restrict__ ei,
                               float* __restrict__ agg,
                               float* __restrict__ cnt,
                               int E, int do_count) {
    int gid = blockIdx.x * blockDim.x + threadIdx.x;
    int warp = gid >> 5;
    int lane = gid & 31;
    if (warp >= E) return;
    int s = __ldg(&ei[warp]);
    int d = __ldg(&ei[E + warp]);
    if ((unsigned)s >= NN || (unsigned)d >= NN) return;  // safety: degrade, don't crash
    const float4* src = reinterpret_cast<const float4*>(feat + (long long)s * 128) + lane;
    float4* dst = reinterpret_cast<float4*>(agg + (long long)d * 128) + lane;
    float4 v = __ldg(src);
    atomicAdd(dst, v);   // sm_90+: native 128-bit RED
    if (do_count && lane == 0) atomicAdd(cnt + d, 1.0f);
}

__global__ void inv_kernel(const float* __restrict__ cnt, float* __restrict__ inv, int n) {
    int i = blockIdx.x * blockDim.x + threadIdx.x;
    if (i < n) inv[i] = 1.0f / fmaxf(cnt[i], 1.0f);
}

// ---------------------------------------------------------------------------
// Fused SAGE layer GEMM:
//   out[m, :] = act( inv[m] * (A1[m,:] @ Wl^T) + A2[m,:] @ Wr^T + bias )
// A1 = agg (numerator), A2 = root features. K = 128 for both phases.
// BM=64, BN = full output width (128 or 64), BK=32, 256 threads, TM=4.
// Mean-scale is applied to accumulators between the two K passes
// (per-output-row scale => no per-element scaling needed).
// ---------------------------------------------------------------------------
template <int BN, int TN, bool RELU>
__global__ void __launch_bounds__(256, 4)
sage_gemm_kernel(const float* __restrict__ A1, const float* __restrict__ A2,
                 const float* __restrict__ inv_cnt,
                 const float* __restrict__ Wl, const float* __restrict__ Wr,
                 const float* __restrict__ bias,
                 float* __restrict__ out, int M) {
    constexpr int BM = 64;
    constexpr int BK = 32;
    constexpr int TM = 4;
    constexpr int K  = 128;

    __shared__ float As[BK][BM];
    __shared__ float Bs[BK][BN];

    const int tid = threadIdx.x;          // 256 threads
    const int tx  = tid & 15;             // 16
    const int ty  = tid >> 4;             // 16
    const int row0 = blockIdx.x * BM;

    float acc[TM][TN];
#pragma unroll
    for (int m = 0; m < TM; ++m)
#pragma unroll
        for (int n = 0; n < TN; ++n) acc[m][n] = 0.f;

#pragma unroll
    for (int phase = 0; phase < 2; ++phase) {
        const float* A = phase ? A2 : A1;
        const float* W = phase ? Wr : Wl;

        for (int k0 = 0; k0 < K; k0 += BK) {
            // --- load A tile (BM x BK), store transposed As[k][m] ---
            {
                const int c = (tid & 7) * 4;   // k within tile
                const int r = tid >> 3;        // 0..31
#pragma unroll
                for (int rr = 0; rr < 2; ++rr) {
                    const int mrow = r + rr * 32;
                    const int grow = row0 + mrow;
                    float4 v = make_float4(0.f, 0.f, 0.f, 0.f);
                    if (grow < M)
                        v = *reinterpret_cast<const float4*>(A + (long long)grow * K + k0 + c);
                    As[c + 0][mrow] = v.x;
                    As[c + 1][mrow] = v.y;
                    As[c + 2][mrow] = v.z;
                    As[c + 3][mrow] = v.w;
                }
            }
            // --- load W tile (BN x BK), store transposed Bs[k][o] ---
            {
                const int c = (tid & 7) * 4;
                const int r = tid >> 3;        // 0..31
#pragma unroll
                for (int rr = 0; rr < BN / 32; ++rr) {
                    const int o = r + rr * 32;
                    float4 v = *reinterpret_cast<const float4*>(W + (long long)o * K + k0 + c);
                    Bs[c + 0][o] = v.x;
                    Bs[c + 1][o] = v.y;
                    Bs[c + 2][o] = v.z;
                    Bs[c + 3][o] = v.w;
                }
            }
            __syncthreads();

#pragma unroll
            for (int kk = 0; kk < BK; ++kk) {
                float4 a4 = *reinterpret_cast<const float4*>(&As[kk][ty * TM]);
                float a[TM] = {a4.x, a4.y, a4.z, a4.w};
                float b[TN];
#pragma unroll
                for (int n = 0; n < TN; n += 4) {
                    float4 b4 = *reinterpret_cast<const float4*>(&Bs[kk][tx * TN + n]);
                    b[n + 0] = b4.x; b[n + 1] = b4.y; b[n + 2] = b4.z; b[n + 3] = b4.w;
                }
#pragma unroll
                for (int m = 0; m < TM; ++m)
#pragma unroll
                    for (int n = 0; n < TN; ++n)
                        acc[m][n] = fmaf(a[m], b[n], acc[m][n]);
            }
            __syncthreads();
        }

        if (phase == 0) {
            // apply mean scale (per output row) before adding root term
#pragma unroll
            for (int m = 0; m < TM; ++m) {
                const int grow = row0 + ty * TM + m;
                const float s = (grow < M) ? inv_cnt[grow] : 0.f;
#pragma unroll
                for (int n = 0; n < TN; ++n) acc[m][n] *= s;
            }
        }
    }

    // epilogue: bias (+ relu), vectorized store
#pragma unroll
    for (int m = 0; m < TM; ++m) {
        const int grow = row0 + ty * TM + m;
        if (grow >= M) continue;
#pragma unroll
        for (int n = 0; n < TN; n += 4) {
            const int col = tx * TN + n;
            float4 v;
            v.x = acc[m][n + 0] + bias[col + 0];
            v.y = acc[m][n + 1] + bias[col + 1];
            v.z = acc[m][n + 2] + bias[col + 2];
            v.w = acc[m][n + 3] + bias[col + 3];
            if (RELU) {
                v.x = fmaxf(v.x, 0.f); v.y = fmaxf(v.y, 0.f);
                v.z = fmaxf(v.z, 0.f); v.w = fmaxf(v.w, 0.f);
            }
            *reinterpret_cast<float4*>(out + (long long)grow * BN + col) = v;
        }
    }
}

// ---------------------------------------------------------------------------
// Decode: warp per label pair, dot of two 64-dim z rows.
// ---------------------------------------------------------------------------
__global__ void decode_kernel(const float* __restrict__ z,
                              const int* __restrict__ eli,
                              float* __restrict__ out, int L) {
    int gid = blockIdx.x * blockDim.x + threadIdx.x;
    int warp = gid >> 5;
    int lane = gid & 31;
    if (warp >= L) return;
    int a = __ldg(&eli[warp]);
    int b = __ldg(&eli[L + warp]);
    float s = 0.f;
    if ((unsigned)a < NN && (unsigned)b < NN) {
        float2 va = *reinterpret_cast<const float2*>(z + (long long)a * 64 + lane * 2);
        float2 vb = *reinterpret_cast<const float2*>(z + (long long)b * 64 + lane * 2);
        s = va.x * vb.x + va.y * vb.y;
    }
#pragma unroll
    for (int off = 16; off > 0; off >>= 1)
        s += __shfl_xor_sync(0xFFFFFFFFu, s, off);
    if (lane == 0) out[warp] = s;
}

// ---------------------------------------------------------------------------
extern "C" void kernel_launch(void* const* d_in, const int* in_sizes, int n_in,
                              void* d_out, int out_size) {
    const float* x   = (const float*)d_in[0];
    const int*   ei  = (const int*)d_in[1];
    const int*   eli = (const int*)d_in[2];
    const float* W1l = (const float*)d_in[3];
    const float* b1  = (const float*)d_in[4];
    const float* W1r = (const float*)d_in[5];
    const float* W2l = (const float*)d_in[6];
    const float* b2  = (const float*)d_in[7];
    const float* W2r = (const float*)d_in[8];
    float* out = (float*)d_out;

    float *agg, *cnt, *inv, *h, *z;
    cudaGetSymbolAddress((void**)&agg, g_agg);
    cudaGetSymbolAddress((void**)&cnt, g_cnt);
    cudaGetSymbolAddress((void**)&inv, g_inv);
    cudaGetSymbolAddress((void**)&h,   g_h);
    cudaGetSymbolAddress((void**)&z,   g_z);

    const int n4 = NN * 32;  // float4 count of agg

    // ---- Layer 1 ----
    zero_kernel<<<2048, 256>>>((float4*)agg, n4, cnt, NN);
    {
        int threads = 256;
        int blocks = (NE * 32 + threads - 1) / threads;
        scatter_kernel<<<blocks, threads>>>(x, ei, agg, cnt, NE, 1);
    }
    inv_kernel<<<(NN + 255) / 256, 256>>>(cnt, inv, NN);
    {
        int blocks = (NN + 63) / 64;
        sage_gemm_kernel<128, 8, true><<<blocks, 256>>>(agg, x, inv, W1l, W1r, b1, h, NN);
    }

    // ---- Layer 2 ----
    zero_kernel<<<2048, 256>>>((float4*)agg, n4, nullptr, 0);
    {
        int threads = 256;
        int blocks = (NE * 32 + threads - 1) / threads;
        scatter_kernel<<<blocks, threads>>>(h, ei, agg, nullptr, NE, 0);
    }
    {
        int blocks = (NN + 63) / 64;
        sage_gemm_kernel<64, 4, false><<<blocks, 256>>>(agg, h, inv, W2l, W2r, b2, z, NN);
    }

    // ---- Decode ----
    {
        int threads = 256;
        int blocks = (NL * 32 + threads - 1) / threads;
        decode_kernel<<<blocks, threads>>>(z, eli, out, NL);
    }
}

// round 3
// speedup vs baseline: 1.4026x; 1.4026x over previous
#include <cuda_runtime.h>
#include <cuda_bf16.h>

#define NN 100000
#define NE 640000
#define NL 100000

// Scratch (device globals: allocation-free rule)
__device__ float g_agg[(size_t)NN * 128];   // layer1 numerator (128 wide); layer2 uses first 64 cols worth
__device__ float g_cnt[NN];
__device__ float g_inv[NN];
__device__ float g_h[(size_t)NN * 128];
__device__ float g_pq[(size_t)NN * 128];    // [p | q] = h @ [W2l | W2r]^T
__device__ float g_z[(size_t)NN * 64];

// ---------------------------------------------------------------------------
__global__ void zero_kernel(float4* a4, int n4, float* cnt, int nc) {
    int i = blockIdx.x * blockDim.x + threadIdx.x;
    int stride = gridDim.x * blockDim.x;
    for (int j = i; j < n4; j += stride)
        a4[j] = make_float4(0.f, 0.f, 0.f, 0.f);
    if (cnt)
        for (int j = i; j < nc; j += stride) cnt[j] = 0.f;
}

// ---------------------------------------------------------------------------
// Scatter (128-wide): warp per edge, lane per float4.
// ---------------------------------------------------------------------------
__global__ void scatter128_kernel(const float* __restrict__ feat,
                                  const int* __restrict__ ei,
                                  float* __restrict__ agg,
                                  float* __restrict__ cnt, int E) {
    int gid = blockIdx.x * blockDim.x + threadIdx.x;
    int e = gid >> 5;
    int lane = gid & 31;
    if (e >= E) return;
    int s = __ldg(&ei[e]);
    int d = __ldg(&ei[E + e]);
    if ((unsigned)s >= NN || (unsigned)d >= NN) return;
    float4 v = __ldg(reinterpret_cast<const float4*>(feat + (long long)s * 128) + lane);
    atomicAdd(reinterpret_cast<float4*>(agg + (long long)d * 128) + lane, v);
    if (lane == 0) atomicAdd(cnt + d, 1.0f);
}

// Scatter (64-wide, reading p = first 64 cols of pq rows): half-warp per edge.
__global__ void scatter64_kernel(const float* __restrict__ pq,
                                 const int* __restrict__ ei,
                                 float* __restrict__ agg64, int E) {
    int gid = blockIdx.x * blockDim.x + threadIdx.x;
    int e = gid >> 4;
    int l = gid & 15;
    if (e >= E) return;
    int s = __ldg(&ei[e]);
    int d = __ldg(&ei[E + e]);
    if ((unsigned)s >= NN || (unsigned)d >= NN) return;
    float4 v = __ldg(reinterpret_cast<const float4*>(pq + (long long)s * 128) + l);
    atomicAdd(reinterpret_cast<float4*>(agg64 + (long long)d * 64) + l, v);
}

__global__ void inv_kernel(const float* __restrict__ cnt, float* __restrict__ inv, int n) {
    int i = blockIdx.x * blockDim.x + threadIdx.x;
    if (i < n) inv[i] = 1.0f / fmaxf(cnt[i], 1.0f);
}

// ---------------------------------------------------------------------------
// Shared GEMM tile machinery: BM=128, BN=128, BK=16, 256 threads, 8x8/thread
// (split as 2x2 blocks of 4x4 at row/col offsets {0,64}).
// As/Bs stored k-major, padded to stride 132 (conflict-free transpose stores).
// ---------------------------------------------------------------------------
#define BM 128
#define BN 128
#define BK 16
#define LDT 132

__device__ __forceinline__ void load_a_tile(float (*As)[LDT], const float* __restrict__ A,
                                            int row0, int k0, int M, int tid) {
#pragma unroll
    for (int i = 0; i < 2; ++i) {
        int f = tid * 2 + i;
        int row = f >> 2;
        int c = (f & 3) * 4;
        float4 v = make_float4(0.f, 0.f, 0.f, 0.f);
        int grow = row0 + row;
        if (grow < M)
            v = *reinterpret_cast<const float4*>(A + (long long)grow * 128 + k0 + c);
        As[c + 0][row] = v.x;
        As[c + 1][row] = v.y;
        As[c + 2][row] = v.z;
        As[c + 3][row] = v.w;
    }
}

__device__ __forceinline__ void compute_tile(float (*As)[LDT], float (*Bs)[LDT],
                                             float acc[8][8], int tx, int ty) {
#pragma unroll
    for (int kk = 0; kk < BK; ++kk) {
        float4 a0 = *reinterpret_cast<const float4*>(&As[kk][ty * 4]);
        float4 a1 = *reinterpret_cast<const float4*>(&As[kk][ty * 4 + 64]);
        float4 b0 = *reinterpret_cast<const float4*>(&Bs[kk][tx * 4]);
        float4 b1 = *reinterpret_cast<const float4*>(&Bs[kk][tx * 4 + 64]);
        float a[8] = {a0.x, a0.y, a0.z, a0.w, a1.x, a1.y, a1.z, a1.w};
        float b[8] = {b0.x, b0.y, b0.z, b0.w, b1.x, b1.y, b1.z, b1.w};
#pragma unroll
        for (int m = 0; m < 8; ++m)
#pragma unroll
            for (int n = 0; n < 8; ++n)
                acc[m][n] = fmaf(a[m], b[n], acc[m][n]);
    }
}

// ---------------------------------------------------------------------------
// Layer 1: h = relu( inv[m]*(agg @ W1l^T) + x @ W1r^T + b1 )
// ---------------------------------------------------------------------------
__global__ void __launch_bounds__(256, 2)
sage1_gemm_kernel(const float* __restrict__ agg, const float* __restrict__ x,
                  const float* __restrict__ inv_cnt,
                  const float* __restrict__ W1l, const float* __restrict__ W1r,
                  const float* __restrict__ b1,
                  float* __restrict__ h, int M) {
    __shared__ float As[BK][LDT];
    __shared__ float Bs[BK][LDT];

    const int tid = threadIdx.x;
    const int tx = tid & 15;
    const int ty = tid >> 4;
    const int row0 = blockIdx.x * BM;

    float acc[8][8];
#pragma unroll
    for (int m = 0; m < 8; ++m)
#pragma unroll
        for (int n = 0; n < 8; ++n) acc[m][n] = 0.f;

#pragma unroll
    for (int phase = 0; phase < 2; ++phase) {
        const float* A = phase ? x : agg;
        const float* W = phase ? W1r : W1l;
        for (int k0 = 0; k0 < 128; k0 += BK) {
            load_a_tile(As, A, row0, k0, M, tid);
            // W tile: rows = output cols (0..127)
#pragma unroll
            for (int i = 0; i < 2; ++i) {
                int f = tid * 2 + i;
                int o = f >> 2;
                int c = (f & 3) * 4;
                float4 v = *reinterpret_cast<const float4*>(W + (long long)o * 128 + k0 + c);
                Bs[c + 0][o] = v.x;
                Bs[c + 1][o] = v.y;
                Bs[c + 2][o] = v.z;
                Bs[c + 3][o] = v.w;
            }
            __syncthreads();
            compute_tile(As, Bs, acc, tx, ty);
            __syncthreads();
        }
        if (phase == 0) {
#pragma unroll
            for (int m = 0; m < 8; ++m) {
                int grow = row0 + ty * 4 + (m < 4 ? m : 60 + m);
                float s = (grow < M) ? inv_cnt[grow] : 0.f;
#pragma unroll
                for (int n = 0; n < 8; ++n) acc[m][n] *= s;
            }
        }
    }

    // epilogue: bias + relu
#pragma unroll
    for (int m = 0; m < 8; ++m) {
        int grow = row0 + ty * 4 + (m < 4 ? m : 60 + m);
        if (grow >= M) continue;
#pragma unroll
        for (int nb = 0; nb < 2; ++nb) {
            int col = tx * 4 + nb * 64;
            float4 bv = *reinterpret_cast<const float4*>(b1 + col);
            float4 v;
            v.x = fmaxf(acc[m][nb * 4 + 0] + bv.x, 0.f);
            v.y = fmaxf(acc[m][nb * 4 + 1] + bv.y, 0.f);
            v.z = fmaxf(acc[m][nb * 4 + 2] + bv.z, 0.f);
            v.w = fmaxf(acc[m][nb * 4 + 3] + bv.w, 0.f);
            *reinterpret_cast<float4*>(h + (long long)grow * 128 + col) = v;
        }
    }
}

// ---------------------------------------------------------------------------
// Layer 2 projection: pq = h @ [W2l | W2r]^T   (cols 0..63 = p, 64..127 = q)
// ---------------------------------------------------------------------------
__global__ void __launch_bounds__(256, 2)
pq_gemm_kernel(const float* __restrict__ h,
               const float* __restrict__ W2l, const float* __restrict__ W2r,
               float* __restrict__ pq, int M) {
    __shared__ float As[BK][LDT];
    __shared__ float Bs[BK][LDT];

    const int tid = threadIdx.x;
    const int tx = tid & 15;
    const int ty = tid >> 4;
    const int row0 = blockIdx.x * BM;

    float acc[8][8];
#pragma unroll
    for (int m = 0; m < 8; ++m)
#pragma unroll
        for (int n = 0; n < 8; ++n) acc[m][n] = 0.f;

    for (int k0 = 0; k0 < 128; k0 += BK) {
        load_a_tile(As, h, row0, k0, M, tid);
#pragma unroll
        for (int i = 0; i < 2; ++i) {
            int f = tid * 2 + i;
            int o = f >> 2;
            int c = (f & 3) * 4;
            const float* Wrow = (o < 64) ? (W2l + (long long)o * 128)
                                         : (W2r + (long long)(o - 64) * 128);
            float4 v = *reinterpret_cast<const float4*>(Wrow + k0 + c);
            Bs[c + 0][o] = v.x;
            Bs[c + 1][o] = v.y;
            Bs[c + 2][o] = v.z;
            Bs[c + 3][o] = v.w;
        }
        __syncthreads();
        compute_tile(As, Bs, acc, tx, ty);
        __syncthreads();
    }

#pragma unroll
    for (int m = 0; m < 8; ++m) {
        int grow = row0 + ty * 4 + (m < 4 ? m : 60 + m);
        if (grow >= M) continue;
#pragma unroll
        for (int nb = 0; nb < 2; ++nb) {
            int col = tx * 4 + nb * 64;
            float4 v = make_float4(acc[m][nb * 4 + 0], acc[m][nb * 4 + 1],
                                   acc[m][nb * 4 + 2], acc[m][nb * 4 + 3]);
            *reinterpret_cast<float4*>(pq + (long long)grow * 128 + col) = v;
        }
    }
}

// ---------------------------------------------------------------------------
// Combine: z[i][j] = inv[i]*agg64[i][j] + pq[i][64+j] + b2[j]   (j < 64)
// ---------------------------------------------------------------------------
__global__ void combine_kernel(const float* __restrict__ agg64,
                               const float* __restrict__ pq,
                               const float* __restrict__ inv_cnt,
                               const float* __restrict__ b2,
                               float* __restrict__ z, int M) {
    int gid = blockIdx.x * blockDim.x + threadIdx.x;
    int node = gid >> 4;
    int l = gid & 15;
    if (node >= M) return;
    float s = inv_cnt[node];
    float4 a = *reinterpret_cast<const float4*>(agg64 + (long long)node * 64 + l * 4);
    float4 q = *reinterpret_cast<const float4*>(pq + (long long)node * 128 + 64 + l * 4);
    float4 b = *reinterpret_cast<const float4*>(b2 + l * 4);
    float4 v;
    v.x = fmaf(s, a.x, q.x + b.x);
    v.y = fmaf(s, a.y, q.y + b.y);
    v.z = fmaf(s, a.z, q.z + b.z);
    v.w = fmaf(s, a.w, q.w + b.w);
    *reinterpret_cast<float4*>(z + (long long)node * 64 + l * 4) = v;
}

// ---------------------------------------------------------------------------
// Decode: warp per label pair, dot of two 64-dim z rows.
// ---------------------------------------------------------------------------
__global__ void decode_kernel(const float* __restrict__ z,
                              const int* __restrict__ eli,
                              float* __restrict__ out, int L) {
    int gid = blockIdx.x * blockDim.x + threadIdx.x;
    int e = gid >> 5;
    int lane = gid & 31;
    if (e >= L) return;
    int a = __ldg(&eli[e]);
    int b = __ldg(&eli[L + e]);
    float s = 0.f;
    if ((unsigned)a < NN && (unsigned)b < NN) {
        float2 va = *reinterpret_cast<const float2*>(z + (long long)a * 64 + lane * 2);
        float2 vb = *reinterpret_cast<const float2*>(z + (long long)b * 64 + lane * 2);
        s = va.x * vb.x + va.y * vb.y;
    }
#pragma unroll
    for (int off = 16; off > 0; off >>= 1)
        s += __shfl_xor_sync(0xFFFFFFFFu, s, off);
    if (lane == 0) out[e] = s;
}

// ---------------------------------------------------------------------------
extern "C" void kernel_launch(void* const* d_in, const int* in_sizes, int n_in,
                              void* d_out, int out_size) {
    const float* x   = (const float*)d_in[0];
    const int*   ei  = (const int*)d_in[1];
    const int*   eli = (const int*)d_in[2];
    const float* W1l = (const float*)d_in[3];
    const float* b1  = (const float*)d_in[4];
    const float* W1r = (const float*)d_in[5];
    const float* W2l = (const float*)d_in[6];
    const float* b2  = (const float*)d_in[7];
    const float* W2r = (const float*)d_in[8];
    float* out = (float*)d_out;

    float *agg, *cnt, *inv, *h, *pq, *z;
    cudaGetSymbolAddress((void**)&agg, g_agg);
    cudaGetSymbolAddress((void**)&cnt, g_cnt);
    cudaGetSymbolAddress((void**)&inv, g_inv);
    cudaGetSymbolAddress((void**)&h,   g_h);
    cudaGetSymbolAddress((void**)&pq,  g_pq);
    cudaGetSymbolAddress((void**)&z,   g_z);

    const int gemm_blocks = (NN + BM - 1) / BM;

    // ---- Layer 1 ----
    zero_kernel<<<2048, 256>>>((float4*)agg, NN * 32, cnt, NN);
    scatter128_kernel<<<(NE * 32 + 255) / 256, 256>>>(x, ei, agg, cnt, NE);
    inv_kernel<<<(NN + 255) / 256, 256>>>(cnt, inv, NN);
    sage1_gemm_kernel<<<gemm_blocks, 256>>>(agg, x, inv, W1l, W1r, b1, h, NN);

    // ---- Layer 2 (projection-before-aggregation) ----
    pq_gemm_kernel<<<gemm_blocks, 256>>>(h, W2l, W2r, pq, NN);
    zero_kernel<<<2048, 256>>>((float4*)agg, NN * 16, nullptr, 0);  // 64-wide
    scatter64_kernel<<<(NE * 16 + 255) / 256, 256>>>(pq, ei, agg, NE);
    combine_kernel<<<(NN * 16 + 255) / 256, 256>>>(agg, pq, inv, b2, z, NN);

    // ---- Decode ----
    decode_kernel<<<(NL * 32 + 255) / 256, 256>>>(z, eli, out, NL);
}

// round 5
// speedup vs baseline: 1.7882x; 1.2749x over previous
#include <cuda_runtime.h>
#include <cuda_bf16.h>
#include <cstdint>

#define NN 100000
#define NE 640000
#define NL 100000

// Scratch (device globals: allocation-free rule)
__device__ float g_agg[(size_t)NN * 128];
__device__ float g_cnt[NN];
__device__ float g_inv[NN];
__device__ float g_h[(size_t)NN * 128];
__device__ float g_pq[(size_t)NN * 128];   // [p | q] = h @ [W2l | W2r]^T
__device__ float g_z[(size_t)NN * 64];

// ---------------------------------------------------------------------------
// bf16 hi/lo split of a float pair, packed as 2x u32 (bf16x2, low half = first)
// ---------------------------------------------------------------------------
__device__ __forceinline__ void split2(float a, float b, uint32_t& hi, uint32_t& lo) {
    __nv_bfloat162 h = __floats2bfloat162_rn(a, b);
    hi = *reinterpret_cast<uint32_t*>(&h);
    __nv_bfloat162 l = __floats2bfloat162_rn(a - __low2float(h), b - __high2float(h));
    lo = *reinterpret_cast<uint32_t*>(&l);
}

// m16n8k16 bf16 mma, fp32 accumulate in place (row.col)
__device__ __forceinline__ void mma16816(float* c, const uint32_t* a, uint32_t b0, uint32_t b1) {
    asm volatile(
        "mma.sync.aligned.m16n8k16.row.col.f32.bf16.bf16.f32 "
        "{%0,%1,%2,%3}, {%4,%5,%6,%7}, {%8,%9}, {%0,%1,%2,%3};"
        : "+f"(c[0]), "+f"(c[1]), "+f"(c[2]), "+f"(c[3])
        : "r"(a[0]), "r"(a[1]), "r"(a[2]), "r"(a[3]), "r"(b0), "r"(b1));
}

// ===========================================================================
// Tensor-core GEMM: out[m, 0:128] = epi( sum_k A[m,k] * B[n,k] )
// MODE 1: A = [inv*agg | x] (K=256), B = [W1l ; W1r] along K, epi = relu(.+b)
// MODE 2: A = h (K=128), B rows = [W2l(0:64) ; W2r(64:128)], epi = identity
// 256 threads, CTA tile 128x128, BK=32, bf16 hi/lo split (3 MMAs per tile).
// SMEM tiles row stride 80B (20 words) -> conflict-free fragment loads.
// ===========================================================================
#define STRIDE_B 80

template <int MODE, bool RELUBIAS>
__global__ void __launch_bounds__(256, 1)
mma_gemm_kernel(const float* __restrict__ A1, const float* __restrict__ A2,
                const float* __restrict__ inv_cnt,
                const float* __restrict__ Wa, const float* __restrict__ Wb,
                const float* __restrict__ bias,
                float* __restrict__ out, int M) {
    __shared__ uint8_t sAh[128 * STRIDE_B];
    __shared__ uint8_t sAl[128 * STRIDE_B];
    __shared__ uint8_t sBh[128 * STRIDE_B];
    __shared__ uint8_t sBl[128 * STRIDE_B];

    const int tid = threadIdx.x;
    const int lane = tid & 31;
    const int wid = tid >> 5;
    const int warp_m = wid & 3;       // 4 row groups of 32
    const int warp_n = wid >> 2;      // 2 col groups of 64
    const int row0 = blockIdx.x * 128;

    const int qrow = lane >> 2;       // 0..7
    const int qk   = (lane & 3) * 4;  // byte offset of k-pair

    // fill indices: thread handles (frow, seg): 16 consecutive floats
    const int frow = tid >> 1;
    const int fseg = tid & 1;
    const int grow = row0 + frow;     // global A row this thread fills
    const bool avalid = grow < M;

    float acc[2][8][4];
#pragma unroll
    for (int i = 0; i < 2; ++i)
#pragma unroll
        for (int j = 0; j < 8; ++j)
#pragma unroll
            for (int q = 0; q < 4; ++q) acc[i][j][q] = 0.f;

    constexpr int KTILES = (MODE == 1) ? 8 : 4;

    for (int t = 0; t < KTILES; ++t) {
        const int k0 = t * 32;
        // ---- A source ----
        const float* asrc;
        float scale = 1.f;
        if (MODE == 1) {
            if (k0 < 128) {
                asrc = A1 + (long long)grow * 128 + k0;
                scale = avalid ? inv_cnt[grow] : 0.f;
            } else {
                asrc = A2 + (long long)grow * 128 + (k0 - 128);
            }
        } else {
            asrc = A1 + (long long)grow * 128 + k0;
        }
        // ---- B source (row n = frow) ----
        const float* bsrc;
        if (MODE == 1)
            bsrc = (k0 < 128 ? Wa + (long long)frow * 128 + k0
                             : Wb + (long long)frow * 128 + (k0 - 128));
        else
            bsrc = (frow < 64 ? Wa + (long long)frow * 128
                              : Wb + (long long)(frow - 64) * 128) + k0;

#pragma unroll
        for (int j = 0; j < 4; ++j) {
            float4 va = avalid ? __ldg(reinterpret_cast<const float4*>(asrc) + fseg * 4 + j)
                               : make_float4(0.f, 0.f, 0.f, 0.f);
            va.x *= scale; va.y *= scale; va.z *= scale; va.w *= scale;
            uint32_t h01, l01, h23, l23;
            split2(va.x, va.y, h01, l01);
            split2(va.z, va.w, h23, l23);
            const int off = frow * STRIDE_B + fseg * 32 + j * 8;
            *reinterpret_cast<uint2*>(sAh + off) = make_uint2(h01, h23);
            *reinterpret_cast<uint2*>(sAl + off) = make_uint2(l01, l23);

            float4 vb = __ldg(reinterpret_cast<const float4*>(bsrc) + fseg * 4 + j);
            split2(vb.x, vb.y, h01, l01);
            split2(vb.z, vb.w, h23, l23);
            *reinterpret_cast<uint2*>(sBh + off) = make_uint2(h01, h23);
            *reinterpret_cast<uint2*>(sBl + off) = make_uint2(l01, l23);
        }
        __syncthreads();

#pragma unroll
        for (int s = 0; s < 2; ++s) {       // two k16 steps per BK=32 tile
            const int kb = s * 32;          // byte offset of k16 chunk
            uint32_t ah[2][4], al[2][4];
#pragma unroll
            for (int i = 0; i < 2; ++i) {
                const int r0 = (warp_m * 32 + i * 16 + qrow) * STRIDE_B + kb + qk;
                const int r8 = r0 + 8 * STRIDE_B;
                ah[i][0] = *reinterpret_cast<const uint32_t*>(sAh + r0);
                ah[i][1] = *reinterpret_cast<const uint32_t*>(sAh + r8);
                ah[i][2] = *reinterpret_cast<const uint32_t*>(sAh + r0 + 16);
                ah[i][3] = *reinterpret_cast<const uint32_t*>(sAh + r8 + 16);
                al[i][0] = *reinterpret_cast<const uint32_t*>(sAl + r0);
                al[i][1] = *reinterpret_cast<const uint32_t*>(sAl + r8);
                al[i][2] = *reinterpret_cast<const uint32_t*>(sAl + r0 + 16);
                al[i][3] = *reinterpret_cast<const uint32_t*>(sAl + r8 + 16);
            }
#pragma unroll
            for (int j = 0; j < 8; ++j) {
                const int n0 = (warp_n * 64 + j * 8 + qrow) * STRIDE_B + kb + qk;
                uint32_t bh0 = *reinterpret_cast<const uint32_t*>(sBh + n0);
                uint32_t bh1 = *reinterpret_cast<const uint32_t*>(sBh + n0 + 16);
                uint32_t bl0 = *reinterpret_cast<const uint32_t*>(sBl + n0);
                uint32_t bl1 = *reinterpret_cast<const uint32_t*>(sBl + n0 + 16);
#pragma unroll
                for (int i = 0; i < 2; ++i) {
                    mma16816(acc[i][j], ah[i], bh0, bh1);
                    mma16816(acc[i][j], ah[i], bl0, bl1);
                    mma16816(acc[i][j], al[i], bh0, bh1);
                }
            }
        }
        __syncthreads();
    }

    // ---- epilogue: c0,c1 -> (row, col), c2,c3 -> (row+8, col) ----
#pragma unroll
    for (int i = 0; i < 2; ++i) {
        const int r = row0 + warp_m * 32 + i * 16 + qrow;
#pragma unroll
        for (int j = 0; j < 8; ++j) {
            const int col = warp_n * 64 + j * 8 + (lane & 3) * 2;
            float2 v0 = make_float2(acc[i][j][0], acc[i][j][1]);
            float2 v1 = make_float2(acc[i][j][2], acc[i][j][3]);
            if (RELUBIAS) {
                float2 bv = *reinterpret_cast<const float2*>(bias + col);
                v0.x = fmaxf(v0.x + bv.x, 0.f); v0.y = fmaxf(v0.y + bv.y, 0.f);
                v1.x = fmaxf(v1.x + bv.x, 0.f); v1.y = fmaxf(v1.y + bv.y, 0.f);
            }
            if (r < M)
                *reinterpret_cast<float2*>(out + (long long)r * 128 + col) = v0;
            if (r + 8 < M)
                *reinterpret_cast<float2*>(out + (long long)(r + 8) * 128 + col) = v1;
        }
    }
}

// ===========================================================================
// Graph kernels (unchanged from passing R3 version)
// ===========================================================================
__global__ void zero_kernel(float4* a4, int n4, float* cnt, int nc) {
    int i = blockIdx.x * blockDim.x + threadIdx.x;
    int stride = gridDim.x * blockDim.x;
    for (int j = i; j < n4; j += stride)
        a4[j] = make_float4(0.f, 0.f, 0.f, 0.f);
    if (cnt)
        for (int j = i; j < nc; j += stride) cnt[j] = 0.f;
}

__global__ void scatter128_kernel(const float* __restrict__ feat,
                                  const int* __restrict__ ei,
                                  float* __restrict__ agg,
                                  float* __restrict__ cnt, int E) {
    int gid = blockIdx.x * blockDim.x + threadIdx.x;
    int e = gid >> 5;
    int lane = gid & 31;
    if (e >= E) return;
    int s = __ldg(&ei[e]);
    int d = __ldg(&ei[E + e]);
    if ((unsigned)s >= NN || (unsigned)d >= NN) return;
    float4 v = __ldg(reinterpret_cast<const float4*>(feat + (long long)s * 128) + lane);
    atomicAdd(reinterpret_cast<float4*>(agg + (long long)d * 128) + lane, v);
    if (lane == 0) atomicAdd(cnt + d, 1.0f);
}

__global__ void scatter64_kernel(const float* __restrict__ pq,
                                 const int* __restrict__ ei,
                                 float* __restrict__ agg64, int E) {
    int gid = blockIdx.x * blockDim.x + threadIdx.x;
    int e = gid >> 4;
    int l = gid & 15;
    if (e >= E) return;
    int s = __ldg(&ei[e]);
    int d = __ldg(&ei[E + e]);
    if ((unsigned)s >= NN || (unsigned)d >= NN) return;
    float4 v = __ldg(reinterpret_cast<const float4*>(pq + (long long)s * 128) + l);
    atomicAdd(reinterpret_cast<float4*>(agg64 + (long long)d * 64) + l, v);
}

__global__ void inv_kernel(const float* __restrict__ cnt, float* __restrict__ inv, int n) {
    int i = blockIdx.x * blockDim.x + threadIdx.x;
    if (i < n) inv[i] = 1.0f / fmaxf(cnt[i], 1.0f);
}

__global__ void combine_kernel(const float* __restrict__ agg64,
                               const float* __restrict__ pq,
                               const float* __restrict__ inv_cnt,
                               const float* __restrict__ b2,
                               float* __restrict__ z, int M) {
    int gid = blockIdx.x * blockDim.x + threadIdx.x;
    int node = gid >> 4;
    int l = gid & 15;
    if (node >= M) return;
    float s = inv_cnt[node];
    float4 a = *reinterpret_cast<const float4*>(agg64 + (long long)node * 64 + l * 4);
    float4 q = *reinterpret_cast<const float4*>(pq + (long long)node * 128 + 64 + l * 4);
    float4 b = *reinterpret_cast<const float4*>(b2 + l * 4);
    float4 v;
    v.x = fmaf(s, a.x, q.x + b.x);
    v.y = fmaf(s, a.y, q.y + b.y);
    v.z = fmaf(s, a.z, q.z + b.z);
    v.w = fmaf(s, a.w, q.w + b.w);
    *reinterpret_cast<float4*>(z + (long long)node * 64 + l * 4) = v;
}

__global__ void decode_kernel(const float* __restrict__ z,
                              const int* __restrict__ eli,
                              float* __restrict__ out, int L) {
    int gid = blockIdx.x * blockDim.x + threadIdx.x;
    int e = gid >> 5;
    int lane = gid & 31;
    if (e >= L) return;
    int a = __ldg(&eli[e]);
    int b = __ldg(&eli[L + e]);
    float s = 0.f;
    if ((unsigned)a < NN && (unsigned)b < NN) {
        float2 va = *reinterpret_cast<const float2*>(z + (long long)a * 64 + lane * 2);
        float2 vb = *reinterpret_cast<const float2*>(z + (long long)b * 64 + lane * 2);
        s = va.x * vb.x + va.y * vb.y;
    }
#pragma unroll
    for (int off = 16; off > 0; off >>= 1)
        s += __shfl_xor_sync(0xFFFFFFFFu, s, off);
    if (lane == 0) out[e] = s;
}

// ===========================================================================
extern "C" void kernel_launch(void* const* d_in, const int* in_sizes, int n_in,
                              void* d_out, int out_size) {
    const float* x   = (const float*)d_in[0];
    const int*   ei  = (const int*)d_in[1];
    const int*   eli = (const int*)d_in[2];
    const float* W1l = (const float*)d_in[3];
    const float* b1  = (const float*)d_in[4];
    const float* W1r = (const float*)d_in[5];
    const float* W2l = (const float*)d_in[6];
    const float* b2  = (const float*)d_in[7];
    const float* W2r = (const float*)d_in[8];
    float* out = (float*)d_out;

    float *agg, *cnt, *inv, *h, *pq, *z;
    cudaGetSymbolAddress((void**)&agg, g_agg);
    cudaGetSymbolAddress((void**)&cnt, g_cnt);
    cudaGetSymbolAddress((void**)&inv, g_inv);
    cudaGetSymbolAddress((void**)&h,   g_h);
    cudaGetSymbolAddress((void**)&pq,  g_pq);
    cudaGetSymbolAddress((void**)&z,   g_z);

    const int gemm_blocks = (NN + 127) / 128;

    // ---- Layer 1 ----
    zero_kernel<<<2048, 256>>>((float4*)agg, NN * 32, cnt, NN);
    scatter128_kernel<<<(NE * 32 + 255) / 256, 256>>>(x, ei, agg, cnt, NE);
    inv_kernel<<<(NN + 255) / 256, 256>>>(cnt, inv, NN);
    mma_gemm_kernel<1, true><<<gemm_blocks, 256>>>(agg, x, inv, W1l, W1r, b1, h, NN);

    // ---- Layer 2 (projection-before-aggregation) ----
    mma_gemm_kernel<2, false><<<gemm_blocks, 256>>>(h, nullptr, nullptr, W2l, W2r, nullptr, pq, NN);
    zero_kernel<<<2048, 256>>>((float4*)agg, NN * 16, nullptr, 0);
    scatter64_kernel<<<(NE * 16 + 255) / 256, 256>>>(pq, ei, agg, NE);
    combine_kernel<<<(NN * 16 + 255) / 256, 256>>>(agg, pq, inv, b2, z, NN);

    // ---- Decode ----
    decode_kernel<<<(NL * 32 + 255) / 256, 256>>>(z, eli, out, NL);
}

// round 6
// speedup vs baseline: 2.1584x; 1.2071x over previous
#include <cuda_runtime.h>
#include <cuda_bf16.h>
#include <cstdint>

#define NN 100000
#define NE 640000
#define NL 100000

// Scratch (device globals: allocation-free rule)
__device__ float g_agg[(size_t)NN * 128];
__device__ float g_cnt[NN];
__device__ float g_inv[NN];
__device__ float g_h[(size_t)NN * 128];
__device__ float g_pq[(size_t)NN * 128];   // [p | q] = h @ [W2l | W2r]^T
__device__ float g_z[(size_t)NN * 64];

// ---------------------------------------------------------------------------
__device__ __forceinline__ uint32_t smem_u32(const void* p) {
    uint32_t a;
    asm("{ .reg .u64 t; cvta.to.shared.u64 t, %1; cvt.u32.u64 %0, t; }" : "=r"(a) : "l"(p));
    return a;
}

__device__ __forceinline__ void cp_async16(uint32_t saddr, const void* gaddr, int src_size) {
    asm volatile("cp.async.cg.shared.global [%0], [%1], 16, %2;"
                 :: "r"(saddr), "l"(gaddr), "r"(src_size) : "memory");
}
#define CP_COMMIT() asm volatile("cp.async.commit_group;" ::: "memory")
#define CP_WAIT(N)  asm volatile("cp.async.wait_group %0;" :: "n"(N) : "memory")

// bf16 hi/lo split of a float pair, packed as 2x u32 (bf16x2, low half = first)
__device__ __forceinline__ void split2(float a, float b, uint32_t& hi, uint32_t& lo) {
    __nv_bfloat162 h = __floats2bfloat162_rn(a, b);
    hi = *reinterpret_cast<uint32_t*>(&h);
    __nv_bfloat162 l = __floats2bfloat162_rn(a - __low2float(h), b - __high2float(h));
    lo = *reinterpret_cast<uint32_t*>(&l);
}

// m16n8k16 bf16 mma, fp32 accumulate in place (row.col)
__device__ __forceinline__ void mma16816(float* c, const uint32_t* a, uint32_t b0, uint32_t b1) {
    asm volatile(
        "mma.sync.aligned.m16n8k16.row.col.f32.bf16.bf16.f32 "
        "{%0,%1,%2,%3}, {%4,%5,%6,%7}, {%8,%9}, {%0,%1,%2,%3};"
        : "+f"(c[0]), "+f"(c[1]), "+f"(c[2]), "+f"(c[3])
        : "r"(a[0]), "r"(a[1]), "r"(a[2]), "r"(a[3]), "r"(b0), "r"(b1));
}

// A-stage geometry (fp32, padded rows)
#define ASTR 272            // bytes per row: 68 floats
#define ASZ  (128 * ASTR)   // one stage = 34816 B

// ===========================================================================
// Persistent tensor-core GEMM: out[m, 0:128] = epi( sum_k A[m,k] * B[n,k] )
// MODE 1: A = [inv*agg | x] (K=256), B = [W1l ; W1r] along K, epi = relu(.+b)
// MODE 2: A = h (K=128), B rows = [W2l(0:64) ; W2r(64:128)], epi = identity
// Weights resident in smem (bf16 hi/lo, converted once per CTA).
// A streamed fp32 via cp.async, 2 stages, split to bf16 hi/lo in fragments.
// ===========================================================================
template <int MODE>
__device__ __forceinline__ void prefetch_chunk(
    int it, int bid, int grid, int M,
    const float* __restrict__ A1, const float* __restrict__ A2,
    const float* __restrict__ inv_cnt,
    uint32_t sA_u32, uint32_t sInv_u32, int tid)
{
    constexpr int NCH = (MODE == 1) ? 4 : 2;
    const int tIdx = it / NCH;
    const int chunk = it % NCH;
    const int row0 = (bid + tIdx * grid) << 7;
    const uint32_t abase = sA_u32 + (it & 1) * ASZ;
    const float* gbase;
    if (MODE == 1)
        gbase = (chunk < 2) ? (A1 + (size_t)row0 * 128 + chunk * 64)
                            : (A2 + (size_t)row0 * 128 + (chunk - 2) * 64);
    else
        gbase = A1 + (size_t)row0 * 128 + chunk * 64;
#pragma unroll
    for (int s = 0; s < 8; ++s) {
        int seg = s * 256 + tid;
        int r = seg >> 4, c = seg & 15;
        bool val = (row0 + r) < M;
        const float* g = gbase + (val ? ((size_t)r * 128 + c * 4) : 0);
        cp_async16(abase + r * ASTR + c * 16, g, val ? 16 : 0);
    }
    if (MODE == 1 && chunk == 0 && tid < 32) {
        int rr = min(row0 + tid * 4, M - 4);
        cp_async16(sInv_u32 + (((tIdx & 1) << 7) + tid * 4) * 4, inv_cnt + rr, 16);
    }
    CP_COMMIT();
}

template <int MODE, bool RELUBIAS>
__global__ void __launch_bounds__(256, 1)
pgemm_kernel(const float* __restrict__ A1, const float* __restrict__ A2,
             const float* __restrict__ inv_cnt,
             const float* __restrict__ Wa, const float* __restrict__ Wb,
             const float* __restrict__ bias,
             float* __restrict__ out, int M)
{
    constexpr int K = (MODE == 1) ? 256 : 128;
    constexpr int NCH = K / 64;
    constexpr int BSTR = (K + 8) * 2;      // bytes per B row (bf16, padded)
    constexpr int SB = 128 * BSTR;

    extern __shared__ uint8_t smem[];
    uint8_t* sBh = smem;
    uint8_t* sBl = smem + SB;
    uint8_t* sA  = smem + 2 * SB;
    float*   sInv = reinterpret_cast<float*>(smem + 2 * SB + 2 * ASZ);

    const int tid = threadIdx.x, lane = tid & 31, wid = tid >> 5;
    const int warp_m = wid & 3, warp_n = wid >> 2;
    const int qrow = lane >> 2;
    const int bid = blockIdx.x, grid = gridDim.x;
    const uint32_t sA_u32 = smem_u32(smem) + 2 * SB;
    const uint32_t sInv_u32 = sA_u32 + 2 * ASZ;

    // ---- convert weights once into resident bf16 hi/lo smem ----
    for (int idx = tid; idx < 128 * (K / 4); idx += 256) {
        int row = idx / (K / 4);
        int k = (idx % (K / 4)) * 4;
        const float* wsrc;
        if (MODE == 1)
            wsrc = (k < 128) ? (Wa + (size_t)row * 128 + k)
                             : (Wb + (size_t)row * 128 + k - 128);
        else
            wsrc = ((row < 64) ? (Wa + (size_t)row * 128)
                               : (Wb + (size_t)(row - 64) * 128)) + k;
        float4 v = __ldg(reinterpret_cast<const float4*>(wsrc));
        uint32_t h01, l01, h23, l23;
        split2(v.x, v.y, h01, l01);
        split2(v.z, v.w, h23, l23);
        *reinterpret_cast<uint2*>(sBh + row * BSTR + k * 2) = make_uint2(h01, h23);
        *reinterpret_cast<uint2*>(sBl + row * BSTR + k * 2) = make_uint2(l01, l23);
    }

    const int ntiles = (M + 127) >> 7;
    if (bid >= ntiles) return;
    const int nmine = (ntiles - bid + grid - 1) / grid;
    const int nIter = nmine * NCH;

    float acc[2][8][4] = {};

    prefetch_chunk<MODE>(0, bid, grid, M, A1, A2, inv_cnt, sA_u32, sInv_u32, tid);

    for (int it = 0; it < nIter; ++it) {
        if (it) __syncthreads();   // protect smem stage reuse across iterations
        if (it + 1 < nIter) {
            prefetch_chunk<MODE>(it + 1, bid, grid, M, A1, A2, inv_cnt, sA_u32, sInv_u32, tid);
            CP_WAIT(1);
        } else {
            CP_WAIT(0);
        }
        __syncthreads();

        const int tIdx = it / NCH, chunk = it % NCH;
        const uint8_t* aS = sA + (it & 1) * ASZ;

        float sc0[2] = {1.f, 1.f}, sc8[2] = {1.f, 1.f};
        if (MODE == 1 && chunk < 2) {
            const float* ib = sInv + ((tIdx & 1) << 7);
#pragma unroll
            for (int i = 0; i < 2; ++i) {
                int rl = warp_m * 32 + i * 16 + qrow;
                sc0[i] = ib[rl];
                sc8[i] = ib[rl + 8];
            }
        }

#pragma unroll
        for (int s = 0; s < 4; ++s) {
            uint32_t ah[2][4], al[2][4];
#pragma unroll
            for (int i = 0; i < 2; ++i) {
                const int rb = (warp_m * 32 + i * 16 + qrow) * ASTR
                             + (s * 16 + (lane & 3) * 2) * 4;
                float2 p0 = *reinterpret_cast<const float2*>(aS + rb);
                float2 p8 = *reinterpret_cast<const float2*>(aS + rb + 8 * ASTR);
                float2 q0 = *reinterpret_cast<const float2*>(aS + rb + 32);
                float2 q8 = *reinterpret_cast<const float2*>(aS + rb + 8 * ASTR + 32);
                split2(p0.x * sc0[i], p0.y * sc0[i], ah[i][0], al[i][0]);
                split2(p8.x * sc8[i], p8.y * sc8[i], ah[i][1], al[i][1]);
                split2(q0.x * sc0[i], q0.y * sc0[i], ah[i][2], al[i][2]);
                split2(q8.x * sc8[i], q8.y * sc8[i], ah[i][3], al[i][3]);
            }
            const int kb2 = (chunk * 64 + s * 16) * 2 + (lane & 3) * 4;
#pragma unroll
            for (int j = 0; j < 8; ++j) {
                const int n0 = (warp_n * 64 + j * 8 + qrow) * BSTR + kb2;
                uint32_t bh0 = *reinterpret_cast<const uint32_t*>(sBh + n0);
                uint32_t bh1 = *reinterpret_cast<const uint32_t*>(sBh + n0 + 16);
                uint32_t bl0 = *reinterpret_cast<const uint32_t*>(sBl + n0);
                uint32_t bl1 = *reinterpret_cast<const uint32_t*>(sBl + n0 + 16);
#pragma unroll
                for (int i = 0; i < 2; ++i) {
                    mma16816(acc[i][j], ah[i], bh0, bh1);
                    mma16816(acc[i][j], ah[i], bl0, bl1);
                    mma16816(acc[i][j], al[i], bh0, bh1);
                }
            }
        }

        if (chunk == NCH - 1) {
            const int row0 = (bid + tIdx * grid) << 7;
#pragma unroll
            for (int i = 0; i < 2; ++i) {
                const int r = row0 + warp_m * 32 + i * 16 + qrow;
#pragma unroll
                for (int j = 0; j < 8; ++j) {
                    const int col = warp_n * 64 + j * 8 + (lane & 3) * 2;
                    float2 v0 = make_float2(acc[i][j][0], acc[i][j][1]);
                    float2 v1 = make_float2(acc[i][j][2], acc[i][j][3]);
                    if (RELUBIAS) {
                        float2 bv = *reinterpret_cast<const float2*>(bias + col);
                        v0.x = fmaxf(v0.x + bv.x, 0.f); v0.y = fmaxf(v0.y + bv.y, 0.f);
                        v1.x = fmaxf(v1.x + bv.x, 0.f); v1.y = fmaxf(v1.y + bv.y, 0.f);
                    }
                    if (r < M)
                        *reinterpret_cast<float2*>(out + (size_t)r * 128 + col) = v0;
                    if (r + 8 < M)
                        *reinterpret_cast<float2*>(out + (size_t)(r + 8) * 128 + col) = v1;
                    acc[i][j][0] = acc[i][j][1] = acc[i][j][2] = acc[i][j][3] = 0.f;
                }
            }
        }
    }
}

// ===========================================================================
// Graph kernels (unchanged, verified)
// ===========================================================================
__global__ void zero_kernel(float4* a4, int n4, float* cnt, int nc) {
    int i = blockIdx.x * blockDim.x + threadIdx.x;
    int stride = gridDim.x * blockDim.x;
    for (int j = i; j < n4; j += stride)
        a4[j] = make_float4(0.f, 0.f, 0.f, 0.f);
    if (cnt)
        for (int j = i; j < nc; j += stride) cnt[j] = 0.f;
}

__global__ void scatter128_kernel(const float* __restrict__ feat,
                                  const int* __restrict__ ei,
                                  float* __restrict__ agg,
                                  float* __restrict__ cnt, int E) {
    int gid = blockIdx.x * blockDim.x + threadIdx.x;
    int e = gid >> 5;
    int lane = gid & 31;
    if (e >= E) return;
    int s = __ldg(&ei[e]);
    int d = __ldg(&ei[E + e]);
    if ((unsigned)s >= NN || (unsigned)d >= NN) return;
    float4 v = __ldg(reinterpret_cast<const float4*>(feat + (long long)s * 128) + lane);
    atomicAdd(reinterpret_cast<float4*>(agg + (long long)d * 128) + lane, v);
    if (lane == 0) atomicAdd(cnt + d, 1.0f);
}

__global__ void scatter64_kernel(const float* __restrict__ pq,
                                 const int* __restrict__ ei,
                                 float* __restrict__ agg64, int E) {
    int gid = blockIdx.x * blockDim.x + threadIdx.x;
    int e = gid >> 4;
    int l = gid & 15;
    if (e >= E) return;
    int s = __ldg(&ei[e]);
    int d = __ldg(&ei[E + e]);
    if ((unsigned)s >= NN || (unsigned)d >= NN) return;
    float4 v = __ldg(reinterpret_cast<const float4*>(pq + (long long)s * 128) + l);
    atomicAdd(reinterpret_cast<float4*>(agg64 + (long long)d * 64) + l, v);
}

__global__ void inv_kernel(const float* __restrict__ cnt, float* __restrict__ inv, int n) {
    int i = blockIdx.x * blockDim.x + threadIdx.x;
    if (i < n) inv[i] = 1.0f / fmaxf(cnt[i], 1.0f);
}

__global__ void combine_kernel(const float* __restrict__ agg64,
                               const float* __restrict__ pq,
                               const float* __restrict__ inv_cnt,
                               const float* __restrict__ b2,
                               float* __restrict__ z, int M) {
    int gid = blockIdx.x * blockDim.x + threadIdx.x;
    int node = gid >> 4;
    int l = gid & 15;
    if (node >= M) return;
    float s = inv_cnt[node];
    float4 a = *reinterpret_cast<const float4*>(agg64 + (long long)node * 64 + l * 4);
    float4 q = *reinterpret_cast<const float4*>(pq + (long long)node * 128 + 64 + l * 4);
    float4 b = *reinterpret_cast<const float4*>(b2 + l * 4);
    float4 v;
    v.x = fmaf(s, a.x, q.x + b.x);
    v.y = fmaf(s, a.y, q.y + b.y);
    v.z = fmaf(s, a.z, q.z + b.z);
    v.w = fmaf(s, a.w, q.w + b.w);
    *reinterpret_cast<float4*>(z + (long long)node * 64 + l * 4) = v;
}

__global__ void decode_kernel(const float* __restrict__ z,
                              const int* __restrict__ eli,
                              float* __restrict__ out, int L) {
    int gid = blockIdx.x * blockDim.x + threadIdx.x;
    int e = gid >> 5;
    int lane = gid & 31;
    if (e >= L) return;
    int a = __ldg(&eli[e]);
    int b = __ldg(&eli[L + e]);
    float s = 0.f;
    if ((unsigned)a < NN && (unsigned)b < NN) {
        float2 va = *reinterpret_cast<const float2*>(z + (long long)a * 64 + lane * 2);
        float2 vb = *reinterpret_cast<const float2*>(z + (long long)b * 64 + lane * 2);
        s = va.x * vb.x + va.y * vb.y;
    }
#pragma unroll
    for (int off = 16; off > 0; off >>= 1)
        s += __shfl_xor_sync(0xFFFFFFFFu, s, off);
    if (lane == 0) out[e] = s;
}

// ===========================================================================
extern "C" void kernel_launch(void* const* d_in, const int* in_sizes, int n_in,
                              void* d_out, int out_size) {
    const float* x   = (const float*)d_in[0];
    const int*   ei  = (const int*)d_in[1];
    const int*   eli = (const int*)d_in[2];
    const float* W1l = (const float*)d_in[3];
    const float* b1  = (const float*)d_in[4];
    const float* W1r = (const float*)d_in[5];
    const float* W2l = (const float*)d_in[6];
    const float* b2  = (const float*)d_in[7];
    const float* W2r = (const float*)d_in[8];
    float* out = (float*)d_out;

    float *agg, *cnt, *inv, *h, *pq, *z;
    cudaGetSymbolAddress((void**)&agg, g_agg);
    cudaGetSymbolAddress((void**)&cnt, g_cnt);
    cudaGetSymbolAddress((void**)&inv, g_inv);
    cudaGetSymbolAddress((void**)&h,   g_h);
    cudaGetSymbolAddress((void**)&pq,  g_pq);
    cudaGetSymbolAddress((void**)&z,   g_z);

    // dynamic smem sizes: 2*B(hi+lo) + 2 A stages + inv buffers
    const int smem1 = 2 * (128 * (256 + 8) * 2) + 2 * ASZ + 1024;  // 205,824
    const int smem2 = 2 * (128 * (128 + 8) * 2) + 2 * ASZ + 1024;  // 140,288
    cudaFuncSetAttribute(pgemm_kernel<1, true>,
                         cudaFuncAttributeMaxDynamicSharedMemorySize, smem1);
    cudaFuncSetAttribute(pgemm_kernel<2, false>,
                         cudaFuncAttributeMaxDynamicSharedMemorySize, smem2);

    const int PGRID = 148;  // persistent: one CTA per SM (B300-safe)

    // ---- Layer 1 ----
    zero_kernel<<<2048, 256>>>((float4*)agg, NN * 32, cnt, NN);
    scatter128_kernel<<<(NE * 32 + 255) / 256, 256>>>(x, ei, agg, cnt, NE);
    inv_kernel<<<(NN + 255) / 256, 256>>>(cnt, inv, NN);
    pgemm_kernel<1, true><<<PGRID, 256, smem1>>>(agg, x, inv, W1l, W1r, b1, h, NN);

    // ---- Layer 2 (projection-before-aggregation) ----
    pgemm_kernel<2, false><<<PGRID, 256, smem2>>>(h, nullptr, nullptr, W2l, W2r, nullptr, pq, NN);
    zero_kernel<<<2048, 256>>>((float4*)agg, NN * 16, nullptr, 0);
    scatter64_kernel<<<(NE * 16 + 255) / 256, 256>>>(pq, ei, agg, NE);
    combine_kernel<<<(NN * 16 + 255) / 256, 256>>>(agg, pq, inv, b2, z, NN);

    // ---- Decode ----
    decode_kernel<<<(NL * 32 + 255) / 256, 256>>>(z, eli, out, NL);
}

// round 7
// speedup vs baseline: 2.1863x; 1.0129x over previous
#include <cuda_runtime.h>
#include <cuda_bf16.h>
#include <cstdint>

#define NN 100000
#define NE 640000
#define NL 100000

// Scratch (device globals: allocation-free rule)
__device__ float g_agg[(size_t)NN * 128];
__device__ float g_cnt[NN];
__device__ float g_inv[NN];
__device__ float g_h[(size_t)NN * 128];
__device__ float g_pq[(size_t)NN * 128];   // [p | q] = h @ [W2l | W2r]^T
__device__ float g_z[(size_t)NN * 64];

// ---------------------------------------------------------------------------
__device__ __forceinline__ uint32_t smem_u32(const void* p) {
    uint32_t a;
    asm("{ .reg .u64 t; cvta.to.shared.u64 t, %1; cvt.u32.u64 %0, t; }" : "=r"(a) : "l"(p));
    return a;
}

__device__ __forceinline__ void cp_async16(uint32_t saddr, const void* gaddr, int src_size) {
    asm volatile("cp.async.cg.shared.global [%0], [%1], 16, %2;"
                 :: "r"(saddr), "l"(gaddr), "r"(src_size) : "memory");
}
#define CP_COMMIT() asm volatile("cp.async.commit_group;" ::: "memory")
#define CP_WAIT(N)  asm volatile("cp.async.wait_group %0;" :: "n"(N) : "memory")

// bf16 hi/lo split of a float pair, packed as 2x u32 (bf16x2)
__device__ __forceinline__ void split2(float a, float b, uint32_t& hi, uint32_t& lo) {
    __nv_bfloat162 h = __floats2bfloat162_rn(a, b);
    hi = *reinterpret_cast<uint32_t*>(&h);
    __nv_bfloat162 l = __floats2bfloat162_rn(a - __low2float(h), b - __high2float(h));
    lo = *reinterpret_cast<uint32_t*>(&l);
}

// m16n8k16 bf16 mma, fp32 accumulate in place (row.col)
__device__ __forceinline__ void mma16816(float* c, const uint32_t* a, uint32_t b0, uint32_t b1) {
    asm volatile(
        "mma.sync.aligned.m16n8k16.row.col.f32.bf16.bf16.f32 "
        "{%0,%1,%2,%3}, {%4,%5,%6,%7}, {%8,%9}, {%0,%1,%2,%3};"
        : "+f"(c[0]), "+f"(c[1]), "+f"(c[2]), "+f"(c[3])
        : "r"(a[0]), "r"(a[1]), "r"(a[2]), "r"(a[3]), "r"(b0), "r"(b1));
}

// A-stage geometry (fp32, 256B data + 32B pad per row: conflict-free LDS.64)
#define ASTR 288
#define ASZ  (128 * ASTR)   // one stage = 36864 B

// ===========================================================================
// Persistent tensor-core GEMM: out[m, 0:128] = epi( sum_k A[m,k] * B[n,k] )
// MODE 1: A = [inv*agg | x] (K=256), B = [W1l ; W1r] along K, epi = relu(.+b)
// MODE 2: A = h (K=128), B rows = [W2l(0:64) ; W2r(64:128)], epi = identity
// 512 threads / 16 warps (warp tile 16x64). Weights resident in smem (bf16
// hi/lo, k16-permuted for LDS.64 fragment loads). A streamed fp32 via
// cp.async, 2 stages, split to bf16 hi/lo in fragments (inv folded in).
// ===========================================================================
template <int MODE>
__device__ __forceinline__ void prefetch_chunk(
    int it, int bid, int grid, int M,
    const float* __restrict__ A1, const float* __restrict__ A2,
    const float* __restrict__ inv_cnt,
    uint32_t sA_u32, uint32_t sInv_u32, int tid)
{
    constexpr int NCH = (MODE == 1) ? 4 : 2;
    const int tIdx = it / NCH;
    const int chunk = it % NCH;
    const int row0 = (bid + tIdx * grid) << 7;
    const uint32_t abase = sA_u32 + (it & 1) * ASZ;
    const float* gbase;
    if (MODE == 1)
        gbase = (chunk < 2) ? (A1 + (size_t)row0 * 128 + chunk * 64)
                            : (A2 + (size_t)row0 * 128 + (chunk - 2) * 64);
    else
        gbase = A1 + (size_t)row0 * 128 + chunk * 64;
#pragma unroll
    for (int s = 0; s < 4; ++s) {
        int seg = s * 512 + tid;
        int r = seg >> 4, c = seg & 15;
        bool val = (row0 + r) < M;
        const float* g = gbase + (val ? ((size_t)r * 128 + c * 4) : 0);
        cp_async16(abase + r * ASTR + c * 16, g, val ? 16 : 0);
    }
    if (MODE == 1 && chunk == 0 && tid < 32) {
        int rr = min(row0 + tid * 4, M - 4);
        cp_async16(sInv_u32 + (((tIdx & 1) << 7) + tid * 4) * 4, inv_cnt + rr, 16);
    }
    CP_COMMIT();
}

template <int MODE, bool RELUBIAS>
__global__ void __launch_bounds__(512, 1)
pgemm_kernel(const float* __restrict__ A1, const float* __restrict__ A2,
             const float* __restrict__ inv_cnt,
             const float* __restrict__ Wa, const float* __restrict__ Wb,
             const float* __restrict__ bias,
             float* __restrict__ out, int M)
{
    constexpr int K = (MODE == 1) ? 256 : 128;
    constexpr int NCH = K / 64;
    constexpr int BSTR = K * 2 + 32;       // bytes per B row (bf16, 32B pad)
    constexpr int SB = 128 * BSTR;

    extern __shared__ uint8_t smem[];
    uint8_t* sBh = smem;
    uint8_t* sBl = smem + SB;
    uint8_t* sA  = smem + 2 * SB;
    float*   sInv = reinterpret_cast<float*>(smem + 2 * SB + 2 * ASZ);

    const int tid = threadIdx.x, lane = tid & 31, wid = tid >> 5;
    const int warp_m = wid & 7, warp_n = wid >> 3;
    const int qrow = lane >> 2;
    const int bid = blockIdx.x, grid = gridDim.x;
    const uint32_t sA_u32 = smem_u32(smem) + 2 * SB;
    const uint32_t sInv_u32 = sA_u32 + 2 * ASZ;

    // ---- convert weights once: bf16 hi/lo, k16-group word-permuted ----
    // group of 8 words (k16): position order (w0,w4,w1,w5,w2,w6,w3,w7)
    for (int idx = tid; idx < 128 * (K / 4); idx += 512) {
        int row = idx / (K / 4);
        int k = (idx % (K / 4)) * 4;
        const float* wsrc;
        if (MODE == 1)
            wsrc = (k < 128) ? (Wa + (size_t)row * 128 + k)
                             : (Wb + (size_t)row * 128 + k - 128);
        else
            wsrc = ((row < 64) ? (Wa + (size_t)row * 128)
                               : (Wb + (size_t)(row - 64) * 128)) + k;
        float4 v = __ldg(reinterpret_cast<const float4*>(wsrc));
        uint32_t h01, l01, h23, l23;
        split2(v.x, v.y, h01, l01);
        split2(v.z, v.w, h23, l23);
        const int base = row * BSTR + (k >> 4) * 32;
        const int km = k & 15;                 // 0,4,8,12
        const int p0 = (km == 0) ? 0 : (km == 4) ? 16 : (km == 8) ? 4 : 20;
        *reinterpret_cast<uint32_t*>(sBh + base + p0)     = h01;
        *reinterpret_cast<uint32_t*>(sBh + base + p0 + 8) = h23;
        *reinterpret_cast<uint32_t*>(sBl + base + p0)     = l01;
        *reinterpret_cast<uint32_t*>(sBl + base + p0 + 8) = l23;
    }

    const int ntiles = (M + 127) >> 7;
    if (bid >= ntiles) return;
    const int nmine = (ntiles - bid + grid - 1) / grid;
    const int nIter = nmine * NCH;

    float acc[8][4] = {};

    prefetch_chunk<MODE>(0, bid, grid, M, A1, A2, inv_cnt, sA_u32, sInv_u32, tid);

    for (int it = 0; it < nIter; ++it) {
        if (it) __syncthreads();   // protect smem stage reuse
        if (it + 1 < nIter) {
            prefetch_chunk<MODE>(it + 1, bid, grid, M, A1, A2, inv_cnt, sA_u32, sInv_u32, tid);
            CP_WAIT(1);
        } else {
            CP_WAIT(0);
        }
        __syncthreads();

        const int tIdx = it / NCH, chunk = it % NCH;
        const uint8_t* aS = sA + (it & 1) * ASZ;

        float sc0 = 1.f, sc8 = 1.f;
        if (MODE == 1 && chunk < 2) {
            const float* ib = sInv + ((tIdx & 1) << 7);
            sc0 = ib[warp_m * 16 + qrow];
            sc8 = ib[warp_m * 16 + qrow + 8];
        }

#pragma unroll
        for (int s = 0; s < 4; ++s) {
            uint32_t ah[4], al[4];
            {
                const int rb = (warp_m * 16 + qrow) * ASTR + (s * 16 + (lane & 3) * 2) * 4;
                float2 p0 = *reinterpret_cast<const float2*>(aS + rb);
                float2 p8 = *reinterpret_cast<const float2*>(aS + rb + 8 * ASTR);
                float2 u0 = *reinterpret_cast<const float2*>(aS + rb + 32);
                float2 u8 = *reinterpret_cast<const float2*>(aS + rb + 8 * ASTR + 32);
                split2(p0.x * sc0, p0.y * sc0, ah[0], al[0]);
                split2(p8.x * sc8, p8.y * sc8, ah[1], al[1]);
                split2(u0.x * sc0, u0.y * sc0, ah[2], al[2]);
                split2(u8.x * sc8, u8.y * sc8, ah[3], al[3]);
            }
            const int gk32 = (chunk * 4 + s) * 32 + (lane & 3) * 8;
#pragma unroll
            for (int j = 0; j < 8; ++j) {
                const int nb = (warp_n * 64 + j * 8 + qrow) * BSTR + gk32;
                uint2 bh = *reinterpret_cast<const uint2*>(sBh + nb);
                uint2 bl = *reinterpret_cast<const uint2*>(sBl + nb);
                mma16816(acc[j], ah, bh.x, bh.y);
                mma16816(acc[j], ah, bl.x, bl.y);
                mma16816(acc[j], al, bh.x, bh.y);
            }
        }

        if (chunk == NCH - 1) {
            const int row0 = (bid + tIdx * grid) << 7;
            const int r = row0 + warp_m * 16 + qrow;
#pragma unroll
            for (int j = 0; j < 8; ++j) {
                const int col = warp_n * 64 + j * 8 + (lane & 3) * 2;
                float2 v0 = make_float2(acc[j][0], acc[j][1]);
                float2 v1 = make_float2(acc[j][2], acc[j][3]);
                if (RELUBIAS) {
                    float2 bv = *reinterpret_cast<const float2*>(bias + col);
                    v0.x = fmaxf(v0.x + bv.x, 0.f); v0.y = fmaxf(v0.y + bv.y, 0.f);
                    v1.x = fmaxf(v1.x + bv.x, 0.f); v1.y = fmaxf(v1.y + bv.y, 0.f);
                }
                if (r < M)
                    *reinterpret_cast<float2*>(out + (size_t)r * 128 + col) = v0;
                if (r + 8 < M)
                    *reinterpret_cast<float2*>(out + (size_t)(r + 8) * 128 + col) = v1;
                acc[j][0] = acc[j][1] = acc[j][2] = acc[j][3] = 0.f;
            }
        }
    }
}

// ===========================================================================
// Graph kernels (unchanged, verified)
// ===========================================================================
__global__ void zero_kernel(float4* a4, int n4, float* cnt, int nc) {
    int i = blockIdx.x * blockDim.x + threadIdx.x;
    int stride = gridDim.x * blockDim.x;
    for (int j = i; j < n4; j += stride)
        a4[j] = make_float4(0.f, 0.f, 0.f, 0.f);
    if (cnt)
        for (int j = i; j < nc; j += stride) cnt[j] = 0.f;
}

__global__ void scatter128_kernel(const float* __restrict__ feat,
                                  const int* __restrict__ ei,
                                  float* __restrict__ agg,
                                  float* __restrict__ cnt, int E) {
    int gid = blockIdx.x * blockDim.x + threadIdx.x;
    int e = gid >> 5;
    int lane = gid & 31;
    if (e >= E) return;
    int s = __ldg(&ei[e]);
    int d = __ldg(&ei[E + e]);
    if ((unsigned)s >= NN || (unsigned)d >= NN) return;
    float4 v = __ldg(reinterpret_cast<const float4*>(feat + (long long)s * 128) + lane);
    atomicAdd(reinterpret_cast<float4*>(agg + (long long)d * 128) + lane, v);
    if (lane == 0) atomicAdd(cnt + d, 1.0f);
}

__global__ void scatter64_kernel(const float* __restrict__ pq,
                                 const int* __restrict__ ei,
                                 float* __restrict__ agg64, int E) {
    int gid = blockIdx.x * blockDim.x + threadIdx.x;
    int e = gid >> 4;
    int l = gid & 15;
    if (e >= E) return;
    int s = __ldg(&ei[e]);
    int d = __ldg(&ei[E + e]);
    if ((unsigned)s >= NN || (unsigned)d >= NN) return;
    float4 v = __ldg(reinterpret_cast<const float4*>(pq + (long long)s * 128) + l);
    atomicAdd(reinterpret_cast<float4*>(agg64 + (long long)d * 64) + l, v);
}

__global__ void inv_kernel(const float* __restrict__ cnt, float* __restrict__ inv, int n) {
    int i = blockIdx.x * blockDim.x + threadIdx.x;
    if (i < n) inv[i] = 1.0f / fmaxf(cnt[i], 1.0f);
}

__global__ void combine_kernel(const float* __restrict__ agg64,
                               const float* __restrict__ pq,
                               const float* __restrict__ inv_cnt,
                               const float* __restrict__ b2,
                               float* __restrict__ z, int M) {
    int gid = blockIdx.x * blockDim.x + threadIdx.x;
    int node = gid >> 4;
    int l = gid & 15;
    if (node >= M) return;
    float s = inv_cnt[node];
    float4 a = *reinterpret_cast<const float4*>(agg64 + (long long)node * 64 + l * 4);
    float4 q = *reinterpret_cast<const float4*>(pq + (long long)node * 128 + 64 + l * 4);
    float4 b = *reinterpret_cast<const float4*>(b2 + l * 4);
    float4 v;
    v.x = fmaf(s, a.x, q.x + b.x);
    v.y = fmaf(s, a.y, q.y + b.y);
    v.z = fmaf(s, a.z, q.z + b.z);
    v.w = fmaf(s, a.w, q.w + b.w);
    *reinterpret_cast<float4*>(z + (long long)node * 64 + l * 4) = v;
}

__global__ void decode_kernel(const float* __restrict__ z,
                              const int* __restrict__ eli,
                              float* __restrict__ out, int L) {
    int gid = blockIdx.x * blockDim.x + threadIdx.x;
    int e = gid >> 5;
    int lane = gid & 31;
    if (e >= L) return;
    int a = __ldg(&eli[e]);
    int b = __ldg(&eli[L + e]);
    float s = 0.f;
    if ((unsigned)a < NN && (unsigned)b < NN) {
        float2 va = *reinterpret_cast<const float2*>(z + (long long)a * 64 + lane * 2);
        float2 vb = *reinterpret_cast<const float2*>(z + (long long)b * 64 + lane * 2);
        s = va.x * vb.x + va.y * vb.y;
    }
#pragma unroll
    for (int off = 16; off > 0; off >>= 1)
        s += __shfl_xor_sync(0xFFFFFFFFu, s, off);
    if (lane == 0) out[e] = s;
}

// ===========================================================================
extern "C" void kernel_launch(void* const* d_in, const int* in_sizes, int n_in,
                              void* d_out, int out_size) {
    const float* x   = (const float*)d_in[0];
    const int*   ei  = (const int*)d_in[1];
    const int*   eli = (const int*)d_in[2];
    const float* W1l = (const float*)d_in[3];
    const float* b1  = (const float*)d_in[4];
    const float* W1r = (const float*)d_in[5];
    const float* W2l = (const float*)d_in[6];
    const float* b2  = (const float*)d_in[7];
    const float* W2r = (const float*)d_in[8];
    float* out = (float*)d_out;

    float *agg, *cnt, *inv, *h, *pq, *z;
    cudaGetSymbolAddress((void**)&agg, g_agg);
    cudaGetSymbolAddress((void**)&cnt, g_cnt);
    cudaGetSymbolAddress((void**)&inv, g_inv);
    cudaGetSymbolAddress((void**)&h,   g_h);
    cudaGetSymbolAddress((void**)&pq,  g_pq);
    cudaGetSymbolAddress((void**)&z,   g_z);

    // dynamic smem: 2*B(hi+lo) + 2 A stages + inv buffers
    const int smem1 = 2 * (128 * (256 * 2 + 32)) + 2 * ASZ + 1024;  // 213,
    const int smem2 = 2 * (128 * (128 * 2 + 32)) + 2 * ASZ + 1024;
    cudaFuncSetAttribute(pgemm_kernel<1, true>,
                         cudaFuncAttributeMaxDynamicSharedMemorySize, smem1);
    cudaFuncSetAttribute(pgemm_kernel<2, false>,
                         cudaFuncAttributeMaxDynamicSharedMemorySize, smem2);

    const int PGRID = 148;  // persistent: one CTA per SM

    // ---- Layer 1 ----
    zero_kernel<<<2048, 256>>>((float4*)agg, NN * 32, cnt, NN);
    scatter128_kernel<<<(NE * 32 + 255) / 256, 256>>>(x, ei, agg, cnt, NE);
    inv_kernel<<<(NN + 255) / 256, 256>>>(cnt, inv, NN);
    pgemm_kernel<1, true><<<PGRID, 512, smem1>>>(agg, x, inv, W1l, W1r, b1, h, NN);

    // ---- Layer 2 (projection-before-aggregation) ----
    pgemm_kernel<2, false><<<PGRID, 512, smem2>>>(h, nullptr, nullptr, W2l, W2r, nullptr, pq, NN);
    zero_kernel<<<2048, 256>>>((float4*)agg, NN * 16, nullptr, 0);
    scatter64_kernel<<<(NE * 16 + 255) / 256, 256>>>(pq, ei, agg, NE);
    combine_kernel<<<(NN * 16 + 255) / 256, 256>>>(agg, pq, inv, b2, z, NN);

    // ---- Decode ----
    decode_kernel<<<(NL * 32 + 255) / 256, 256>>>(z, eli, out, NL);
}

// round 8
// speedup vs baseline: 2.7443x; 1.2552x over previous
#include <cuda_runtime.h>
#include <cuda_bf16.h>
#include <cstdint>

#define NN 100000
#define NE 640000
#define NL 100000
#define SCAN_BLK 512
#define NSCAN ((NN + SCAN_BLK - 1) / SCAN_BLK)

// Scratch (device globals: allocation-free rule)
__device__ float g_agg[(size_t)NN * 128];     // layer-1 mean aggregate
__device__ float g_h[(size_t)NN * 128];
__device__ float g_pq[(size_t)NN * 128];      // [p | q] = h @ [W2l | W2r]^T
__device__ float g_z[(size_t)NN * 64];
// CSR scratch
__device__ int g_deg[NN];
__device__ int g_excl[NN];
__device__ int g_bsum[NSCAN];
__device__ int g_boff[NSCAN];
__device__ int g_rowptr[NN + 1];
__device__ int g_cursor[NN];
__device__ int g_srcs[NE];

// ---------------------------------------------------------------------------
__device__ __forceinline__ uint32_t smem_u32(const void* p) {
    uint32_t a;
    asm("{ .reg .u64 t; cvta.to.shared.u64 t, %1; cvt.u32.u64 %0, t; }" : "=r"(a) : "l"(p));
    return a;
}

__device__ __forceinline__ void cp_async16(uint32_t saddr, const void* gaddr, int src_size) {
    asm volatile("cp.async.cg.shared.global [%0], [%1], 16, %2;"
                 :: "r"(saddr), "l"(gaddr), "r"(src_size) : "memory");
}
#define CP_COMMIT() asm volatile("cp.async.commit_group;" ::: "memory")
#define CP_WAIT(N)  asm volatile("cp.async.wait_group %0;" :: "n"(N) : "memory")

// bf16 hi/lo split of a float pair, packed as 2x u32 (bf16x2)
__device__ __forceinline__ void split2(float a, float b, uint32_t& hi, uint32_t& lo) {
    __nv_bfloat162 h = __floats2bfloat162_rn(a, b);
    hi = *reinterpret_cast<uint32_t*>(&h);
    __nv_bfloat162 l = __floats2bfloat162_rn(a - __low2float(h), b - __high2float(h));
    lo = *reinterpret_cast<uint32_t*>(&l);
}

// m16n8k16 bf16 mma, fp32 accumulate in place (row.col)
__device__ __forceinline__ void mma16816(float* c, const uint32_t* a, uint32_t b0, uint32_t b1) {
    asm volatile(
        "mma.sync.aligned.m16n8k16.row.col.f32.bf16.bf16.f32 "
        "{%0,%1,%2,%3}, {%4,%5,%6,%7}, {%8,%9}, {%0,%1,%2,%3};"
        : "+f"(c[0]), "+f"(c[1]), "+f"(c[2]), "+f"(c[3])
        : "r"(a[0]), "r"(a[1]), "r"(a[2]), "r"(a[3]), "r"(b0), "r"(b1));
}

#define ASTR 288
#define ASZ  (128 * ASTR)

// ===========================================================================
// Persistent tensor-core GEMM (R7 structure, inv machinery removed)
// MODE 1: A = [agg_mean | x] (K=256), B = [W1l ; W1r], epi = relu(.+b1)
// MODE 2: A = h (K=128), B rows = [W2l(0:64) ; W2r(64:128)], epi = identity
// ===========================================================================
template <int MODE>
__device__ __forceinline__ void prefetch_chunk(
    int it, int bid, int grid, int M,
    const float* __restrict__ A1, const float* __restrict__ A2,
    uint32_t sA_u32, int tid)
{
    constexpr int NCH = (MODE == 1) ? 4 : 2;
    const int tIdx = it / NCH;
    const int chunk = it % NCH;
    const int row0 = (bid + tIdx * grid) << 7;
    const uint32_t abase = sA_u32 + (it & 1) * ASZ;
    const float* gbase;
    if (MODE == 1)
        gbase = (chunk < 2) ? (A1 + (size_t)row0 * 128 + chunk * 64)
                            : (A2 + (size_t)row0 * 128 + (chunk - 2) * 64);
    else
        gbase = A1 + (size_t)row0 * 128 + chunk * 64;
#pragma unroll
    for (int s = 0; s < 4; ++s) {
        int seg = s * 512 + tid;
        int r = seg >> 4, c = seg & 15;
        bool val = (row0 + r) < M;
        const float* g = gbase + (val ? ((size_t)r * 128 + c * 4) : 0);
        cp_async16(abase + r * ASTR + c * 16, g, val ? 16 : 0);
    }
    CP_COMMIT();
}

template <int MODE, bool RELUBIAS>
__global__ void __launch_bounds__(512, 1)
pgemm_kernel(const float* __restrict__ A1, const float* __restrict__ A2,
             const float* __restrict__ Wa, const float* __restrict__ Wb,
             const float* __restrict__ bias,
             float* __restrict__ out, int M)
{
    constexpr int K = (MODE == 1) ? 256 : 128;
    constexpr int NCH = K / 64;
    constexpr int BSTR = K * 2 + 32;
    constexpr int SB = 128 * BSTR;

    extern __shared__ uint8_t smem[];
    uint8_t* sBh = smem;
    uint8_t* sBl = smem + SB;
    uint8_t* sA  = smem + 2 * SB;

    const int tid = threadIdx.x, lane = tid & 31, wid = tid >> 5;
    const int warp_m = wid & 7, warp_n = wid >> 3;
    const int qrow = lane >> 2;
    const int bid = blockIdx.x, grid = gridDim.x;
    const uint32_t sA_u32 = smem_u32(smem) + 2 * SB;

    // ---- convert weights once: bf16 hi/lo, k16-group word-permuted ----
    for (int idx = tid; idx < 128 * (K / 4); idx += 512) {
        int row = idx / (K / 4);
        int k = (idx % (K / 4)) * 4;
        const float* wsrc;
        if (MODE == 1)
            wsrc = (k < 128) ? (Wa + (size_t)row * 128 + k)
                             : (Wb + (size_t)row * 128 + k - 128);
        else
            wsrc = ((row < 64) ? (Wa + (size_t)row * 128)
                               : (Wb + (size_t)(row - 64) * 128)) + k;
        float4 v = __ldg(reinterpret_cast<const float4*>(wsrc));
        uint32_t h01, l01, h23, l23;
        split2(v.x, v.y, h01, l01);
        split2(v.z, v.w, h23, l23);
        const int base = row * BSTR + (k >> 4) * 32;
        const int km = k & 15;
        const int p0 = (km == 0) ? 0 : (km == 4) ? 16 : (km == 8) ? 4 : 20;
        *reinterpret_cast<uint32_t*>(sBh + base + p0)     = h01;
        *reinterpret_cast<uint32_t*>(sBh + base + p0 + 8) = h23;
        *reinterpret_cast<uint32_t*>(sBl + base + p0)     = l01;
        *reinterpret_cast<uint32_t*>(sBl + base + p0 + 8) = l23;
    }

    const int ntiles = (M + 127) >> 7;
    if (bid >= ntiles) return;
    const int nmine = (ntiles - bid + grid - 1) / grid;
    const int nIter = nmine * NCH;

    float acc[8][4] = {};

    prefetch_chunk<MODE>(0, bid, grid, M, A1, A2, sA_u32, tid);

    for (int it = 0; it < nIter; ++it) {
        if (it) __syncthreads();
        if (it + 1 < nIter) {
            prefetch_chunk<MODE>(it + 1, bid, grid, M, A1, A2, sA_u32, tid);
            CP_WAIT(1);
        } else {
            CP_WAIT(0);
        }
        __syncthreads();

        const int tIdx = it / NCH, chunk = it % NCH;
        const uint8_t* aS = sA + (it & 1) * ASZ;

#pragma unroll
        for (int s = 0; s < 4; ++s) {
            uint32_t ah[4], al[4];
            {
                const int rb = (warp_m * 16 + qrow) * ASTR + (s * 16 + (lane & 3) * 2) * 4;
                float2 p0 = *reinterpret_cast<const float2*>(aS + rb);
                float2 p8 = *reinterpret_cast<const float2*>(aS + rb + 8 * ASTR);
                float2 u0 = *reinterpret_cast<const float2*>(aS + rb + 32);
                float2 u8 = *reinterpret_cast<const float2*>(aS + rb + 8 * ASTR + 32);
                split2(p0.x, p0.y, ah[0], al[0]);
                split2(p8.x, p8.y, ah[1], al[1]);
                split2(u0.x, u0.y, ah[2], al[2]);
                split2(u8.x, u8.y, ah[3], al[3]);
            }
            const int gk32 = (chunk * 4 + s) * 32 + (lane & 3) * 8;
#pragma unroll
            for (int j = 0; j < 8; ++j) {
                const int nb = (warp_n * 64 + j * 8 + qrow) * BSTR + gk32;
                uint2 bh = *reinterpret_cast<const uint2*>(sBh + nb);
                uint2 bl = *reinterpret_cast<const uint2*>(sBl + nb);
                mma16816(acc[j], ah, bh.x, bh.y);
                mma16816(acc[j], ah, bl.x, bl.y);
                mma16816(acc[j], al, bh.x, bh.y);
            }
        }

        if (chunk == NCH - 1) {
            const int row0 = (bid + tIdx * grid) << 7;
            const int r = row0 + warp_m * 16 + qrow;
#pragma unroll
            for (int j = 0; j < 8; ++j) {
                const int col = warp_n * 64 + j * 8 + (lane & 3) * 2;
                float2 v0 = make_float2(acc[j][0], acc[j][1]);
                float2 v1 = make_float2(acc[j][2], acc[j][3]);
                if (RELUBIAS) {
                    float2 bv = *reinterpret_cast<const float2*>(bias + col);
                    v0.x = fmaxf(v0.x + bv.x, 0.f); v0.y = fmaxf(v0.y + bv.y, 0.f);
                    v1.x = fmaxf(v1.x + bv.x, 0.f); v1.y = fmaxf(v1.y + bv.y, 0.f);
                }
                if (r < M)
                    *reinterpret_cast<float2*>(out + (size_t)r * 128 + col) = v0;
                if (r + 8 < M)
                    *reinterpret_cast<float2*>(out + (size_t)(r + 8) * 128 + col) = v1;
                acc[j][0] = acc[j][1] = acc[j][2] = acc[j][3] = 0.f;
            }
        }
    }
}

// ===========================================================================
// CSR build: histogram -> 3-phase exclusive scan -> slot fill
// ===========================================================================
__global__ void zero_deg_kernel(int* deg, int n) {
    int i = blockIdx.x * blockDim.x + threadIdx.x;
    if (i < n) deg[i] = 0;
}

__global__ void hist_kernel(const int* __restrict__ ei, int* __restrict__ deg, int E) {
    int e = blockIdx.x * blockDim.x + threadIdx.x;
    if (e >= E) return;
    int d = __ldg(&ei[E + e]);
    if ((unsigned)d < NN) atomicAdd(&deg[d], 1);
}

__global__ void scan1_kernel(const int* __restrict__ deg, int* __restrict__ excl,
                             int* __restrict__ bsum, int n) {
    __shared__ int sh[SCAN_BLK];
    int b = blockIdx.x;
    int i = b * SCAN_BLK + threadIdx.x;
    int v = (i < n) ? deg[i] : 0;
    sh[threadIdx.x] = v;
    __syncthreads();
#pragma unroll
    for (int off = 1; off < SCAN_BLK; off <<= 1) {
        int t = (threadIdx.x >= off) ? sh[threadIdx.x - off] : 0;
        __syncthreads();
        sh[threadIdx.x] += t;
        __syncthreads();
    }
    if (i < n) excl[i] = sh[threadIdx.x] - v;
    if (threadIdx.x == SCAN_BLK - 1) bsum[b] = sh[SCAN_BLK - 1];
}

__global__ void scan2_kernel(const int* __restrict__ bsum, int* __restrict__ boff, int nb) {
    if (threadIdx.x == 0 && blockIdx.x == 0) {
        int run = 0;
        for (int b = 0; b < nb; ++b) { boff[b] = run; run += bsum[b]; }
    }
}

__global__ void scan3_kernel(const int* __restrict__ excl, const int* __restrict__ boff,
                             int* __restrict__ rowptr, int* __restrict__ cursor, int n, int total) {
    int i = blockIdx.x * blockDim.x + threadIdx.x;
    if (i < n) {
        int v = excl[i] + boff[i / SCAN_BLK];
        rowptr[i] = v;
        cursor[i] = v;
    }
    if (i == 0) rowptr[n] = total;
}

__global__ void fill_kernel(const int* __restrict__ ei, int* __restrict__ cursor,
                            int* __restrict__ srcs, int E) {
    int e = blockIdx.x * blockDim.x + threadIdx.x;
    if (e >= E) return;
    int s = __ldg(&ei[e]);
    int d = __ldg(&ei[E + e]);
    if ((unsigned)s >= NN || (unsigned)d >= NN) return;
    int slot = atomicAdd(&cursor[d], 1);
    srcs[slot] = s;
}

// ===========================================================================
// Aggregation (no atomics): warp per node
// ===========================================================================
__global__ void agg1_kernel(const float* __restrict__ x,
                            const int* __restrict__ rowptr,
                            const int* __restrict__ srcs,
                            float* __restrict__ agg) {
    int gid = blockIdx.x * blockDim.x + threadIdx.x;
    int n = gid >> 5, lane = gid & 31;
    if (n >= NN) return;
    int beg = __ldg(&rowptr[n]), end = __ldg(&rowptr[n + 1]);
    float4 acc = make_float4(0.f, 0.f, 0.f, 0.f);
    for (int i = beg; i < end; ++i) {
        int s = __ldg(&srcs[i]);
        float4 v = __ldg(reinterpret_cast<const float4*>(x + (size_t)s * 128) + lane);
        acc.x += v.x; acc.y += v.y; acc.z += v.z; acc.w += v.w;
    }
    float sc = 1.f / fmaxf((float)(end - beg), 1.f);
    acc.x *= sc; acc.y *= sc; acc.z *= sc; acc.w *= sc;
    reinterpret_cast<float4*>(agg + (size_t)n * 128)[lane] = acc;
}

// layer-2 aggregation of p (cols 0..63 of pq) fused with combine:
// z[n][j] = mean_p[n][j] + pq[n][64+j] + b2[j]
__global__ void agg2z_kernel(const float* __restrict__ pq,
                             const int* __restrict__ rowptr,
                             const int* __restrict__ srcs,
                             const float* __restrict__ b2,
                             float* __restrict__ z) {
    int gid = blockIdx.x * blockDim.x + threadIdx.x;
    int n = gid >> 5, lane = gid & 31;
    if (n >= NN) return;
    int beg = __ldg(&rowptr[n]), end = __ldg(&rowptr[n + 1]);
    float2 acc = make_float2(0.f, 0.f);
    for (int i = beg; i < end; ++i) {
        int s = __ldg(&srcs[i]);
        float2 v = __ldg(reinterpret_cast<const float2*>(pq + (size_t)s * 128) + lane);
        acc.x += v.x; acc.y += v.y;
    }
    float sc = 1.f / fmaxf((float)(end - beg), 1.f);
    float2 q = __ldg(reinterpret_cast<const float2*>(pq + (size_t)n * 128 + 64) + lane);
    float2 bv = *reinterpret_cast<const float2*>(b2 + lane * 2);
    float2 r;
    r.x = fmaf(acc.x, sc, q.x + bv.x);
    r.y = fmaf(acc.y, sc, q.y + bv.y);
    *reinterpret_cast<float2*>(z + (size_t)n * 64 + lane * 2) = r;
}

// ===========================================================================
__global__ void decode_kernel(const float* __restrict__ z,
                              const int* __restrict__ eli,
                              float* __restrict__ out, int L) {
    int gid = blockIdx.x * blockDim.x + threadIdx.x;
    int e = gid >> 5;
    int lane = gid & 31;
    if (e >= L) return;
    int a = __ldg(&eli[e]);
    int b = __ldg(&eli[L + e]);
    float s = 0.f;
    if ((unsigned)a < NN && (unsigned)b < NN) {
        float2 va = *reinterpret_cast<const float2*>(z + (size_t)a * 64 + lane * 2);
        float2 vb = *reinterpret_cast<const float2*>(z + (size_t)b * 64 + lane * 2);
        s = va.x * vb.x + va.y * vb.y;
    }
#pragma unroll
    for (int off = 16; off > 0; off >>= 1)
        s += __shfl_xor_sync(0xFFFFFFFFu, s, off);
    if (lane == 0) out[e] = s;
}

// ===========================================================================
extern "C" void kernel_launch(void* const* d_in, const int* in_sizes, int n_in,
                              void* d_out, int out_size) {
    const float* x   = (const float*)d_in[0];
    const int*   ei  = (const int*)d_in[1];
    const int*   eli = (const int*)d_in[2];
    const float* W1l = (const float*)d_in[3];
    const float* b1  = (const float*)d_in[4];
    const float* W1r = (const float*)d_in[5];
    const float* W2l = (const float*)d_in[6];
    const float* b2  = (const float*)d_in[7];
    const float* W2r = (const float*)d_in[8];
    float* out = (float*)d_out;

    float *agg, *h, *pq, *z;
    int *deg, *excl, *bsum, *boff, *rowptr, *cursor, *srcs;
    cudaGetSymbolAddress((void**)&agg, g_agg);
    cudaGetSymbolAddress((void**)&h,   g_h);
    cudaGetSymbolAddress((void**)&pq,  g_pq);
    cudaGetSymbolAddress((void**)&z,   g_z);
    cudaGetSymbolAddress((void**)&deg, g_deg);
    cudaGetSymbolAddress((void**)&excl, g_excl);
    cudaGetSymbolAddress((void**)&bsum, g_bsum);
    cudaGetSymbolAddress((void**)&boff, g_boff);
    cudaGetSymbolAddress((void**)&rowptr, g_rowptr);
    cudaGetSymbolAddress((void**)&cursor, g_cursor);
    cudaGetSymbolAddress((void**)&srcs, g_srcs);

    const int smem1 = 2 * (128 * (256 * 2 + 32)) + 2 * ASZ + 1024;
    const int smem2 = 2 * (128 * (128 * 2 + 32)) + 2 * ASZ + 1024;
    cudaFuncSetAttribute(pgemm_kernel<1, true>,
                         cudaFuncAttributeMaxDynamicSharedMemorySize, smem1);
    cudaFuncSetAttribute(pgemm_kernel<2, false>,
                         cudaFuncAttributeMaxDynamicSharedMemorySize, smem2);
    const int PGRID = 148;

    // ---- CSR build (shared by both layers) ----
    zero_deg_kernel<<<(NN + 255) / 256, 256>>>(deg, NN);
    hist_kernel<<<(NE + 255) / 256, 256>>>(ei, deg, NE);
    scan1_kernel<<<NSCAN, SCAN_BLK>>>(deg, excl, bsum, NN);
    scan2_kernel<<<1, 32>>>(bsum, boff, NSCAN);
    scan3_kernel<<<(NN + 255) / 256, 256>>>(excl, boff, rowptr, cursor, NN, NE);
    fill_kernel<<<(NE + 255) / 256, 256>>>(ei, cursor, srcs, NE);

    // ---- Layer 1 ----
    agg1_kernel<<<(NN * 32 + 255) / 256, 256>>>(x, rowptr, srcs, agg);
    pgemm_kernel<1, true><<<PGRID, 512, smem1>>>(agg, x, W1l, W1r, b1, h, NN);

    // ---- Layer 2 (projection-before-aggregation) ----
    pgemm_kernel<2, false><<<PGRID, 512, smem2>>>(h, nullptr, W2l, W2r, nullptr, pq, NN);
    agg2z_kernel<<<(NN * 32 + 255) / 256, 256>>>(pq, rowptr, srcs, b2, z);

    // ---- Decode ----
    decode_kernel<<<(NL * 32 + 255) / 256, 256>>>(z, eli, out, NL);
}